// round 1
// baseline (speedup 1.0000x reference)
#include <cuda_runtime.h>
#include <math.h>

// GeodesicLoss: reference initializes velocity to zero, so the geodesic ODE
// acc = -Gamma v v is identically zero for all 10 steps -> traj == outputs.
// The result is exactly mean_b || outputs_b - targets_b ||_2.
// Pure streaming reduction over 128 MiB -> DRAM-bound.

#define B_ROWS   524288
#define D_DIM    32
#define THREADS  256
#define ROWS_PER_BLOCK (THREADS / 8)              // 32
#define NBLOCKS  (B_ROWS / ROWS_PER_BLOCK)        // 16384

__device__ float g_partials[NBLOCKS];

__global__ __launch_bounds__(THREADS)
void geodesic_rownorm_kernel(const float* __restrict__ outputs,
                             const float* __restrict__ targets) {
    const int tid  = blockIdx.x * THREADS + threadIdx.x;
    const int row  = tid >> 3;              // 8 lanes per row
    const int sub  = threadIdx.x & 7;       // which float4 of the row

    const float4* __restrict__ o4 = reinterpret_cast<const float4*>(outputs);
    const float4* __restrict__ t4 = reinterpret_cast<const float4*>(targets);

    const int idx = row * (D_DIM / 4) + sub;
    float4 a = o4[idx];
    float4 b = t4[idx];

    float dx = a.x - b.x;
    float dy = a.y - b.y;
    float dz = a.z - b.z;
    float dw = a.w - b.w;
    float s = dx * dx + dy * dy + dz * dz + dw * dw;

    // Reduce the 8 lanes covering this row (butterfly -> all 8 hold row sum)
    s += __shfl_xor_sync(0xFFFFFFFFu, s, 1);
    s += __shfl_xor_sync(0xFFFFFFFFu, s, 2);
    s += __shfl_xor_sync(0xFFFFFFFFu, s, 4);

    // One representative lane per row contributes sqrt(row_sum)
    float v = (sub == 0) ? sqrtf(s) : 0.0f;

    // Sum the 4 row-norms held in this warp (lanes 0,8,16,24)
    v += __shfl_xor_sync(0xFFFFFFFFu, v, 8);
    v += __shfl_xor_sync(0xFFFFFFFFu, v, 16);

    __shared__ float wsum[THREADS / 32];
    if ((threadIdx.x & 31) == 0)
        wsum[threadIdx.x >> 5] = v;
    __syncthreads();

    if (threadIdx.x < (THREADS / 32)) {
        float w = wsum[threadIdx.x];
        w += __shfl_xor_sync(0x000000FFu, w, 1);
        w += __shfl_xor_sync(0x000000FFu, w, 2);
        w += __shfl_xor_sync(0x000000FFu, w, 4);
        if (threadIdx.x == 0)
            g_partials[blockIdx.x] = w;
    }
}

// Deterministic final reduction: fixed traversal order, no float atomics.
__global__ __launch_bounds__(1024)
void geodesic_final_reduce_kernel(float* __restrict__ out) {
    __shared__ float sm[1024];
    float s = 0.0f;
    // 16384 / 1024 = 16 strided loads per thread, fixed order
    #pragma unroll
    for (int i = threadIdx.x; i < NBLOCKS; i += 1024)
        s += g_partials[i];
    sm[threadIdx.x] = s;
    __syncthreads();
    #pragma unroll
    for (int stride = 512; stride > 0; stride >>= 1) {
        if (threadIdx.x < stride)
            sm[threadIdx.x] += sm[threadIdx.x + stride];
        __syncthreads();
    }
    if (threadIdx.x == 0)
        out[0] = sm[0] * (1.0f / (float)B_ROWS);
}

extern "C" void kernel_launch(void* const* d_in, const int* in_sizes, int n_in,
                              void* d_out, int out_size) {
    const float* outputs = (const float*)d_in[0];
    const float* targets = (const float*)d_in[1];
    // d_in[2] (christoffel_symbols) is mathematically dead: vel starts at 0.
    float* out = (float*)d_out;

    geodesic_rownorm_kernel<<<NBLOCKS, THREADS>>>(outputs, targets);
    geodesic_final_reduce_kernel<<<1, 1024>>>(out);
}

// round 2
// speedup vs baseline: 1.0118x; 1.0118x over previous
#include <cuda_runtime.h>
#include <math.h>

// GeodesicLoss: reference initializes velocity to zero, so the geodesic ODE
// acc = -Gamma v v is identically zero for all 10 steps -> traj == outputs.
// Result is exactly mean_b || outputs_b - targets_b ||_2.
// Pure streaming reduction over 128 MiB -> DRAM-bound.
//
// Single fused kernel: per-block partials + last-block-done final reduce
// (fixed summation order -> deterministic; counter self-resets for graph replay).

#define B_ROWS   524288
#define D_DIM    32
#define THREADS  256
#define NBLOCKS  1024
#define ROWS_PER_ITER   (THREADS / 8)                      // 32 rows per block-iter
#define ITERS    (B_ROWS / (NBLOCKS * ROWS_PER_ITER))      // 16

__device__ float        g_partials[NBLOCKS];
__device__ unsigned int g_done_count = 0;

__global__ __launch_bounds__(THREADS)
void geodesic_loss_fused_kernel(const float* __restrict__ outputs,
                                const float* __restrict__ targets,
                                float* __restrict__ out) {
    const int sub      = threadIdx.x & 7;          // which float4 of the row
    const int row_in_b = threadIdx.x >> 3;         // row slot within block-iter
    const int base_row = blockIdx.x * (ROWS_PER_ITER * ITERS);

    const float4* __restrict__ o4 = reinterpret_cast<const float4*>(outputs);
    const float4* __restrict__ t4 = reinterpret_cast<const float4*>(targets);

    float acc = 0.0f;

    #pragma unroll 4
    for (int it = 0; it < ITERS; it++) {
        const int row = base_row + it * ROWS_PER_ITER + row_in_b;
        const int idx = row * (D_DIM / 4) + sub;

        float4 a = __ldcs(&o4[idx]);
        float4 b = __ldcs(&t4[idx]);

        float dx = a.x - b.x;
        float dy = a.y - b.y;
        float dz = a.z - b.z;
        float dw = a.w - b.w;
        float s = dx * dx + dy * dy + dz * dz + dw * dw;

        // Reduce the 8 lanes covering this row
        s += __shfl_xor_sync(0xFFFFFFFFu, s, 1);
        s += __shfl_xor_sync(0xFFFFFFFFu, s, 2);
        s += __shfl_xor_sync(0xFFFFFFFFu, s, 4);

        if (sub == 0)
            acc += sqrtf(s);
    }

    // Combine the 4 row-accumulators per warp (lanes 0,8,16,24 nonzero)
    acc += __shfl_xor_sync(0xFFFFFFFFu, acc, 8);
    acc += __shfl_xor_sync(0xFFFFFFFFu, acc, 16);

    __shared__ float wsum[THREADS / 32];
    if ((threadIdx.x & 31) == 0)
        wsum[threadIdx.x >> 5] = acc;
    __syncthreads();

    __shared__ bool s_is_last;
    if (threadIdx.x == 0) {
        float bsum = 0.0f;
        #pragma unroll
        for (int i = 0; i < THREADS / 32; i++)
            bsum += wsum[i];
        g_partials[blockIdx.x] = bsum;
        __threadfence();
        unsigned int prev = atomicAdd(&g_done_count, 1u);
        s_is_last = (prev == NBLOCKS - 1);
    }
    __syncthreads();

    if (s_is_last) {
        // Final reduce over NBLOCKS partials, fixed order -> deterministic.
        float s = 0.0f;
        #pragma unroll
        for (int i = threadIdx.x; i < NBLOCKS; i += THREADS)
            s += g_partials[i];

        // intra-warp butterfly
        s += __shfl_xor_sync(0xFFFFFFFFu, s, 1);
        s += __shfl_xor_sync(0xFFFFFFFFu, s, 2);
        s += __shfl_xor_sync(0xFFFFFFFFu, s, 4);
        s += __shfl_xor_sync(0xFFFFFFFFu, s, 8);
        s += __shfl_xor_sync(0xFFFFFFFFu, s, 16);

        __shared__ float fsum[THREADS / 32];
        if ((threadIdx.x & 31) == 0)
            fsum[threadIdx.x >> 5] = s;
        __syncthreads();

        if (threadIdx.x == 0) {
            float tot = 0.0f;
            #pragma unroll
            for (int i = 0; i < THREADS / 32; i++)
                tot += fsum[i];
            out[0] = tot * (1.0f / (float)B_ROWS);
            g_done_count = 0;   // reset for next graph replay
        }
    }
}

extern "C" void kernel_launch(void* const* d_in, const int* in_sizes, int n_in,
                              void* d_out, int out_size) {
    const float* outputs = (const float*)d_in[0];
    const float* targets = (const float*)d_in[1];
    // d_in[2] (christoffel_symbols) is mathematically dead: vel starts at 0.
    float* out = (float*)d_out;

    geodesic_loss_fused_kernel<<<NBLOCKS, THREADS>>>(outputs, targets, out);
}

// round 3
// speedup vs baseline: 1.0931x; 1.0804x over previous
#include <cuda_runtime.h>
#include <math.h>

// GeodesicLoss: reference initializes velocity to zero, so the geodesic ODE
// acc = -Gamma v v is identically zero for all 10 steps -> traj == outputs.
// Result is exactly mean_b || outputs_b - targets_b ||_2.
// Pure streaming reduction over 128 MiB -> DRAM-bound.
//
// R3: front-batched 8x LDG.128 per thread (explicit MLP), fused
// last-block-done final reduce (fixed order -> deterministic, counter
// self-resets for graph replay).

#define B_ROWS   524288
#define D_DIM    32
#define THREADS  256
#define NBLOCKS  4096
#define ROWS_PER_ITER (THREADS / 8)                         // 32 rows / block-iter
#define ITERS 4                                             // 128 rows / block
// sanity: NBLOCKS * ROWS_PER_ITER * ITERS == B_ROWS
#define F4_PER_ITER (ROWS_PER_ITER * (D_DIM / 4))           // 256 float4 stride

__device__ float        g_partials[NBLOCKS];
__device__ unsigned int g_done_count = 0;

__global__ __launch_bounds__(THREADS)
void geodesic_loss_fused_kernel(const float* __restrict__ outputs,
                                const float* __restrict__ targets,
                                float* __restrict__ out) {
    const int sub      = threadIdx.x & 7;          // which float4 of the row
    const int row_in_b = threadIdx.x >> 3;         // row slot within block-iter
    const int base_row = blockIdx.x * (ROWS_PER_ITER * ITERS);

    const float4* __restrict__ o4 = reinterpret_cast<const float4*>(outputs);
    const float4* __restrict__ t4 = reinterpret_cast<const float4*>(targets);

    const int idx0 = (base_row + row_in_b) * (D_DIM / 4) + sub;

    // ---- front-batched loads: 8 independent LDG.128 in flight ----
    float4 a0 = __ldcs(&o4[idx0 + 0 * F4_PER_ITER]);
    float4 a1 = __ldcs(&o4[idx0 + 1 * F4_PER_ITER]);
    float4 a2 = __ldcs(&o4[idx0 + 2 * F4_PER_ITER]);
    float4 a3 = __ldcs(&o4[idx0 + 3 * F4_PER_ITER]);
    float4 b0 = __ldcs(&t4[idx0 + 0 * F4_PER_ITER]);
    float4 b1 = __ldcs(&t4[idx0 + 1 * F4_PER_ITER]);
    float4 b2 = __ldcs(&t4[idx0 + 2 * F4_PER_ITER]);
    float4 b3 = __ldcs(&t4[idx0 + 3 * F4_PER_ITER]);

    float dx, dy, dz, dw;
    #define SSQ(a, b) (dx = a.x - b.x, dy = a.y - b.y, dz = a.z - b.z, \
                       dw = a.w - b.w, dx*dx + dy*dy + dz*dz + dw*dw)
    float s0 = SSQ(a0, b0);
    float s1 = SSQ(a1, b1);
    float s2 = SSQ(a2, b2);
    float s3 = SSQ(a3, b3);
    #undef SSQ

    // Reduce the 8 lanes covering each row (4 independent chains)
    s0 += __shfl_xor_sync(0xFFFFFFFFu, s0, 1);
    s1 += __shfl_xor_sync(0xFFFFFFFFu, s1, 1);
    s2 += __shfl_xor_sync(0xFFFFFFFFu, s2, 1);
    s3 += __shfl_xor_sync(0xFFFFFFFFu, s3, 1);
    s0 += __shfl_xor_sync(0xFFFFFFFFu, s0, 2);
    s1 += __shfl_xor_sync(0xFFFFFFFFu, s1, 2);
    s2 += __shfl_xor_sync(0xFFFFFFFFu, s2, 2);
    s3 += __shfl_xor_sync(0xFFFFFFFFu, s3, 2);
    s0 += __shfl_xor_sync(0xFFFFFFFFu, s0, 4);
    s1 += __shfl_xor_sync(0xFFFFFFFFu, s1, 4);
    s2 += __shfl_xor_sync(0xFFFFFFFFu, s2, 4);
    s3 += __shfl_xor_sync(0xFFFFFFFFu, s3, 4);

    float acc = 0.0f;
    if (sub == 0)
        acc = sqrtf(s0) + sqrtf(s1) + sqrtf(s2) + sqrtf(s3);

    // Combine the 4 row-accumulators per warp (lanes 0,8,16,24 nonzero)
    acc += __shfl_xor_sync(0xFFFFFFFFu, acc, 8);
    acc += __shfl_xor_sync(0xFFFFFFFFu, acc, 16);

    __shared__ float wsum[THREADS / 32];
    if ((threadIdx.x & 31) == 0)
        wsum[threadIdx.x >> 5] = acc;
    __syncthreads();

    __shared__ bool s_is_last;
    if (threadIdx.x == 0) {
        float bsum = 0.0f;
        #pragma unroll
        for (int i = 0; i < THREADS / 32; i++)
            bsum += wsum[i];
        g_partials[blockIdx.x] = bsum;
        __threadfence();
        unsigned int prev = atomicAdd(&g_done_count, 1u);
        s_is_last = (prev == NBLOCKS - 1);
    }
    __syncthreads();

    if (s_is_last) {
        // Final reduce over NBLOCKS partials via float4, fixed order.
        const float4* __restrict__ p4 =
            reinterpret_cast<const float4*>(g_partials);
        float s = 0.0f;
        #pragma unroll
        for (int i = threadIdx.x; i < NBLOCKS / 4; i += THREADS) {
            float4 v = p4[i];
            s += (v.x + v.y) + (v.z + v.w);
        }

        s += __shfl_xor_sync(0xFFFFFFFFu, s, 1);
        s += __shfl_xor_sync(0xFFFFFFFFu, s, 2);
        s += __shfl_xor_sync(0xFFFFFFFFu, s, 4);
        s += __shfl_xor_sync(0xFFFFFFFFu, s, 8);
        s += __shfl_xor_sync(0xFFFFFFFFu, s, 16);

        __shared__ float fsum[THREADS / 32];
        if ((threadIdx.x & 31) == 0)
            fsum[threadIdx.x >> 5] = s;
        __syncthreads();

        if (threadIdx.x == 0) {
            float tot = 0.0f;
            #pragma unroll
            for (int i = 0; i < THREADS / 32; i++)
                tot += fsum[i];
            out[0] = tot * (1.0f / (float)B_ROWS);
            g_done_count = 0;   // reset for next graph replay
        }
    }
}

extern "C" void kernel_launch(void* const* d_in, const int* in_sizes, int n_in,
                              void* d_out, int out_size) {
    const float* outputs = (const float*)d_in[0];
    const float* targets = (const float*)d_in[1];
    // d_in[2] (christoffel_symbols) is mathematically dead: vel starts at 0.
    float* out = (float*)d_out;

    geodesic_loss_fused_kernel<<<NBLOCKS, THREADS>>>(outputs, targets, out);
}